// round 14
// baseline (speedup 1.0000x reference)
#include <cuda_runtime.h>
#include <cstdint>
#include <cstddef>

typedef unsigned long long ull;

#define T_STEPS 2048
#define HDIM 32
#define DIN 6
#define WARPS_PER_CTA 4
#define CHUNK 64
#define NCHUNK (T_STEPS / CHUNK)

#define CBAR() asm volatile("" ::: "memory")

__device__ __forceinline__ ull fma2(ull a, ull b, ull c) {
    ull r;
    asm("fma.rn.f32x2 %0, %1, %2, %3;" : "=l"(r) : "l"(a), "l"(b), "l"(c));
    return r;
}
__device__ __forceinline__ ull add2(ull a, ull b) {
    ull r;
    asm("add.rn.f32x2 %0, %1, %2;" : "=l"(r) : "l"(a), "l"(b));
    return r;
}
__device__ __forceinline__ float hsum2(ull a) {
    float lo, hi;
    asm("mov.b64 {%0, %1}, %2;" : "=f"(lo), "=f"(hi) : "l"(a));
    return lo + hi;
}
__device__ __forceinline__ ull pack2(float lo, float hi) {
    ull r;
    asm("mov.b64 %0, {%1, %2};" : "=l"(r) : "f"(lo), "f"(hi));
    return r;
}
__device__ __forceinline__ float tanh_mufu(float x) {
    float r;
    asm("tanh.approx.f32 %0, %1;" : "=f"(r) : "f"(x));
    return r;
}

__device__ __forceinline__ uint32_t smem_u32(const void* p) {
    return (uint32_t)__cvta_generic_to_shared(p);
}
__device__ __forceinline__ void cp16(uint32_t saddr, const void* gaddr) {
    asm volatile("cp.async.cg.shared.global [%0], [%1], 16;" :: "r"(saddr), "l"(gaddr));
}
__device__ __forceinline__ void cp_commit() { asm volatile("cp.async.commit_group;"); }
__device__ __forceinline__ void cp_wait1()  { asm volatile("cp.async.wait_group 1;"); }

// stage one 1536B x-chunk into shared (3 x 16B per lane)
__device__ __forceinline__ void stage_chunk(float* dst, const float* src, int j) {
    uint32_t s = smem_u32(dst) + j * 16;
    const char* g = (const char*)src + j * 16;
    cp16(s,        g);
    cp16(s + 512,  g + 512);
    cp16(s + 1024, g + 1024);
    cp_commit();
}

// RNN cell (layers 1,2): tanh( Wp . hin + Wr . hprev + bias ), bias folded into a0 init
__device__ __forceinline__ float cell(const ull (&wp)[16], const float* hin,
                                      const ull (&wr)[16], const float* hprev,
                                      ull biasp) {
    ull a0 = biasp, a1 = 0ull, a2 = 0ull, a3 = 0ull;
    const ulonglong2* hp = reinterpret_cast<const ulonglong2*>(hin);
    const ulonglong2* hr = reinterpret_cast<const ulonglong2*>(hprev);
#pragma unroll
    for (int p = 0; p < 8; p++) {
        ulonglong2 u = hp[p];           // LDS.128 broadcast
        a0 = fma2(u.x, wp[2 * p],     a0);
        a1 = fma2(u.y, wp[2 * p + 1], a1);
        ulonglong2 v = hr[p];
        a2 = fma2(v.x, wr[2 * p],     a2);
        a3 = fma2(v.y, wr[2 * p + 1], a3);
    }
    a0 = add2(add2(a0, a1), add2(a2, a3));
    return tanh_mufu(hsum2(a0));
}

// layer-0 cell: x-projection (D=6 -> 3 pairs) + recurrence, bias folded
__device__ __forceinline__ float cell0(const ull (&wx)[3], const float* xp,
                                       const ull (&wr)[16], const float* hprev,
                                       ull biasp) {
    const ull* xq = reinterpret_cast<const ull*>(xp);   // 8B-aligned pairs
    ull a0 = fma2(xq[0], wx[0], biasp);
    a0 = fma2(xq[1], wx[1], a0);
    a0 = fma2(xq[2], wx[2], a0);
    ull a1 = 0ull, a2 = 0ull;
    const ulonglong2* hr = reinterpret_cast<const ulonglong2*>(hprev);
#pragma unroll
    for (int p = 0; p < 8; p++) {
        ulonglong2 v = hr[p];
        a1 = fma2(v.x, wr[2 * p],     a1);
        a2 = fma2(v.y, wr[2 * p + 1], a2);
    }
    a0 = add2(a0, add2(a1, a2));
    return tanh_mufu(hsum2(a0));
}

__global__ void __launch_bounds__(WARPS_PER_CTA * 32, 1)
rnn3_fused_kernel(const float* __restrict__ x,
                  const float* __restrict__ Wih0,
                  const float* __restrict__ WihR,
                  const float* __restrict__ Whh,
                  const float* __restrict__ bih,
                  const float* __restrict__ bhh,
                  const float* __restrict__ fcw,
                  const float* __restrict__ fcb,
                  float* __restrict__ out) {
    // Six DISTINCT shared objects (layer x parity): provably alias-free, so
    // store-ASAP never fences the next cell's loads.
    __shared__ __align__(16) float h0E[WARPS_PER_CTA][HDIM];
    __shared__ __align__(16) float h0O[WARPS_PER_CTA][HDIM];
    __shared__ __align__(16) float h1E[WARPS_PER_CTA][HDIM];
    __shared__ __align__(16) float h1O[WARPS_PER_CTA][HDIM];
    __shared__ __align__(16) float h2E[WARPS_PER_CTA][HDIM];
    __shared__ __align__(16) float h2O[WARPS_PER_CTA][HDIM];
    __shared__ __align__(16) float xs[WARPS_PER_CTA][2][CHUNK * DIN];

    const int tid = threadIdx.x;
    const int w = tid >> 5;
    const int j = tid & 31;
    const int b = blockIdx.x * WARPS_PER_CTA + w;

    // zero all h state
    h0E[w][j] = 0.0f; h0O[w][j] = 0.0f;
    h1E[w][j] = 0.0f; h1O[w][j] = 0.0f;
    h2E[w][j] = 0.0f; h2O[w][j] = 0.0f;
    __syncthreads();

    // ---- weights in registers as packed f32x2 pairs ----
    ull wx0[3], wr0[16], wp1[16], wr1[16], wp2[16], wr2[16];
    {
        const ull* q = reinterpret_cast<const ull*>(Wih0 + j * DIN);
        wx0[0] = q[0]; wx0[1] = q[1]; wx0[2] = q[2];
    }
    {
        const ull* q0 = reinterpret_cast<const ull*>(Whh  + (0 * HDIM + j) * HDIM);
        const ull* q1 = reinterpret_cast<const ull*>(Whh  + (1 * HDIM + j) * HDIM);
        const ull* q2 = reinterpret_cast<const ull*>(Whh  + (2 * HDIM + j) * HDIM);
        const ull* p1 = reinterpret_cast<const ull*>(WihR + (0 * HDIM + j) * HDIM);
        const ull* p2 = reinterpret_cast<const ull*>(WihR + (1 * HDIM + j) * HDIM);
#pragma unroll
        for (int k = 0; k < 16; k++) {
            wr0[k] = q0[k]; wr1[k] = q1[k]; wr2[k] = q2[k];
            wp1[k] = p1[k]; wp2[k] = p2[k];
        }
    }
    const ull bp0 = pack2(bih[0 * HDIM + j] + bhh[0 * HDIM + j], 0.0f);
    const ull bp1 = pack2(bih[1 * HDIM + j] + bhh[1 * HDIM + j], 0.0f);
    const ull bp2 = pack2(bih[2 * HDIM + j] + bhh[2 * HDIM + j], 0.0f);

    // ---- x staging via cp.async: chunk0 + chunk1 in flight (register-free) ----
    const float* gx = x + (size_t)b * (T_STEPS * DIN);
    float* xb[2] = { &xs[w][0][0], &xs[w][1][0] };

    stage_chunk(xb[0], gx, j);                         // group: chunk0
    stage_chunk(xb[1], gx + CHUNK * DIN, j);           // group: chunk1
    cp_wait1();                                        // chunk0 ready
    CBAR();

    float h2last = 0.0f;

    // even timestep (pw=0, pr=1): store each h ASAP; arrays are alias-free.
    auto iterE = [&](const float* xp) {
        float n0 = cell0(wx0, xp, wr0, &h0O[w][0], bp0);
        h0E[w][j] = n0;
        float n1 = cell(wp1, &h0O[w][0], wr1, &h1E[w][0], bp1);
        h1O[w][j] = n1;
        float n2 = cell(wp2, &h1E[w][0], wr2, &h2O[w][0], bp2);
        h2E[w][j] = n2;
    };
    // odd timestep (pw=1, pr=0)
    auto iterO = [&](const float* xp) {
        float n0 = cell0(wx0, xp, wr0, &h0E[w][0], bp0);
        h0O[w][j] = n0;
        float n1 = cell(wp1, &h0E[w][0], wr1, &h1O[w][0], bp1);
        h1E[w][j] = n1;
        float n2 = cell(wp2, &h1O[w][0], wr2, &h2E[w][0], bp2);
        h2O[w][j] = n2;
    };

    // ---- prologue peels ----
    {   // i = 0 (pw=0): only L0; h0[-1] = h0O = zeros
        float n0 = cell0(wx0, &xs[w][0][0 * DIN], wr0, &h0O[w][0], bp0);
        h0E[w][j] = n0;
    }
    {   // i = 1 (pw=1): L0 + L1; h1[-1] = h1O = zeros
        float n0 = cell0(wx0, &xs[w][0][1 * DIN], wr0, &h0E[w][0], bp0);
        h0O[w][j] = n0;
        float n1 = cell(wp1, &h0E[w][0], wr1, &h1O[w][0], bp1);
        h1E[w][j] = n1;
    }

    // ---- main loop over chunks: i = 2 .. 2047 ----
#pragma unroll 1
    for (int c = 0; c < NCHUNK; c++) {
        const float* xrow = xb[c & 1];
        const int s0 = (c == 0) ? 2 : 0;
#pragma unroll 2
        for (int s = s0; s < CHUNK; s += 2) {
            iterE(xrow + s * DIN);              // even global t
            iterO(xrow + (s + 1) * DIN);        // odd global t
        }
        // prefetch chunk c+2 into the buffer just consumed, then wait for c+1
        if (c + 2 < NCHUNK)
            stage_chunk(xb[c & 1], gx + (c + 2) * CHUNK * DIN, j);
        else
            cp_commit();                        // keep group accounting uniform
        cp_wait1();                             // chunk c+1 resident
        CBAR();
    }

    // ---- epilogue peels ----
    {   // i = 2048 (pw=0, pr=1): L1(2047) + L2(2046)
        float n1 = cell(wp1, &h0O[w][0], wr1, &h1E[w][0], bp1);
        h1O[w][j] = n1;
        float n2 = cell(wp2, &h1E[w][0], wr2, &h2O[w][0], bp2);
        h2E[w][j] = n2;
    }
    {   // i = 2049 (pw=1, pr=0): L2(2047) -> final hidden state, keep in register
        h2last = cell(wp2, &h1O[w][0], wr2, &h2E[w][0], bp2);
    }

    // ---- FC head: out[b,c] = sum_j h2last_j * fcw[c,j] + fcb[c] ----
    float s0v = h2last * fcw[0 * HDIM + j];
    float s1v = h2last * fcw[1 * HDIM + j];
    float s2v = h2last * fcw[2 * HDIM + j];
    float s3v = h2last * fcw[3 * HDIM + j];
    float s4v = h2last * fcw[4 * HDIM + j];
    float s5v = h2last * fcw[5 * HDIM + j];
#pragma unroll
    for (int off = 16; off; off >>= 1) {
        s0v += __shfl_xor_sync(0xffffffffu, s0v, off);
        s1v += __shfl_xor_sync(0xffffffffu, s1v, off);
        s2v += __shfl_xor_sync(0xffffffffu, s2v, off);
        s3v += __shfl_xor_sync(0xffffffffu, s3v, off);
        s4v += __shfl_xor_sync(0xffffffffu, s4v, off);
        s5v += __shfl_xor_sync(0xffffffffu, s5v, off);
    }
    float v = s0v;
    if (j == 1) v = s1v;
    if (j == 2) v = s2v;
    if (j == 3) v = s3v;
    if (j == 4) v = s4v;
    if (j == 5) v = s5v;
    if (j < 6) out[b * 6 + j] = v + fcb[j];
}

extern "C" void kernel_launch(void* const* d_in, const int* in_sizes, int n_in,
                              void* d_out, int out_size) {
    const float* x    = (const float*)d_in[0];
    const float* Wih0 = (const float*)d_in[1];
    const float* WihR = (const float*)d_in[2];
    const float* Whh  = (const float*)d_in[3];
    const float* bih  = (const float*)d_in[4];
    const float* bhh  = (const float*)d_in[5];
    const float* fcw  = (const float*)d_in[6];
    const float* fcb  = (const float*)d_in[7];

    const int B = in_sizes[0] / (T_STEPS * DIN);   // 512
    rnn3_fused_kernel<<<B / WARPS_PER_CTA, WARPS_PER_CTA * 32>>>(
        x, Wih0, WihR, Whh, bih, bhh, fcw, fcb, (float*)d_out);
}

// round 15
// speedup vs baseline: 1.0765x; 1.0765x over previous
#include <cuda_runtime.h>
#include <cstdint>
#include <cstddef>

typedef unsigned long long ull;

#define T_STEPS 2048
#define HDIM 32
#define DIN 6
#define WARPS_PER_CTA 4
#define CHUNK 64
#define NCHUNK (T_STEPS / CHUNK)

#define CBAR() asm volatile("" ::: "memory")

__device__ __forceinline__ ull fma2(ull a, ull b, ull c) {
    ull r;
    asm("fma.rn.f32x2 %0, %1, %2, %3;" : "=l"(r) : "l"(a), "l"(b), "l"(c));
    return r;
}
__device__ __forceinline__ ull add2(ull a, ull b) {
    ull r;
    asm("add.rn.f32x2 %0, %1, %2;" : "=l"(r) : "l"(a), "l"(b));
    return r;
}
__device__ __forceinline__ float hsum2(ull a) {
    float lo, hi;
    asm("mov.b64 {%0, %1}, %2;" : "=f"(lo), "=f"(hi) : "l"(a));
    return lo + hi;
}
__device__ __forceinline__ ull pack2(float lo, float hi) {
    ull r;
    asm("mov.b64 %0, {%1, %2};" : "=l"(r) : "f"(lo), "f"(hi));
    return r;
}
__device__ __forceinline__ float tanh_mufu(float x) {
    float r;
    asm("tanh.approx.f32 %0, %1;" : "=f"(r) : "f"(x));
    return r;
}

// RNN cell with the cross-layer matrix Wp in SHARED memory ([pair][lane] layout,
// lane j reads wps[p*32] with wps = &wpXs[0][j]) and recurrent Wr in registers.
// Weight LDS.64s ride the LSU pipe in parallel with the fma pipe.
__device__ __forceinline__ float cellS(const ull* wps, const float* hin,
                                       const ull (&wr)[16], const float* hprev,
                                       ull biasp) {
    ull a0 = biasp, a1 = 0ull, a2 = 0ull, a3 = 0ull;
    const ulonglong2* hp = reinterpret_cast<const ulonglong2*>(hin);
    const ulonglong2* hr = reinterpret_cast<const ulonglong2*>(hprev);
#pragma unroll
    for (int p = 0; p < 8; p++) {
        ulonglong2 u = hp[p];           // LDS.128 broadcast
        a0 = fma2(u.x, wps[(2 * p) * 32],     a0);
        a1 = fma2(u.y, wps[(2 * p + 1) * 32], a1);
        ulonglong2 v = hr[p];
        a2 = fma2(v.x, wr[2 * p],     a2);
        a3 = fma2(v.y, wr[2 * p + 1], a3);
    }
    a0 = add2(add2(a0, a1), add2(a2, a3));
    return tanh_mufu(hsum2(a0));
}

// layer-0 cell: x-projection (register weights) + recurrence (register weights)
__device__ __forceinline__ float cell0(const ull (&wx)[3], const float* xp,
                                       const ull (&wr)[16], const float* hprev,
                                       ull biasp) {
    const ull* xq = reinterpret_cast<const ull*>(xp);
    ull a0 = fma2(xq[0], wx[0], biasp);
    a0 = fma2(xq[1], wx[1], a0);
    a0 = fma2(xq[2], wx[2], a0);
    ull a1 = 0ull, a2 = 0ull;
    const ulonglong2* hr = reinterpret_cast<const ulonglong2*>(hprev);
#pragma unroll
    for (int p = 0; p < 8; p++) {
        ulonglong2 v = hr[p];
        a1 = fma2(v.x, wr[2 * p],     a1);
        a2 = fma2(v.y, wr[2 * p + 1], a2);
    }
    a0 = add2(a0, add2(a1, a2));
    return tanh_mufu(hsum2(a0));
}

__global__ void __launch_bounds__(WARPS_PER_CTA * 32, 1)
rnn3_fused_kernel(const float* __restrict__ x,
                  const float* __restrict__ Wih0,
                  const float* __restrict__ WihR,
                  const float* __restrict__ Whh,
                  const float* __restrict__ bih,
                  const float* __restrict__ bhh,
                  const float* __restrict__ fcw,
                  const float* __restrict__ fcb,
                  float* __restrict__ out) {
    // Six DISTINCT h objects (layer x parity): provably alias-free -> store-ASAP
    // never fences the next cell's loads (legality).
    __shared__ __align__(16) float h0E[WARPS_PER_CTA][HDIM];
    __shared__ __align__(16) float h0O[WARPS_PER_CTA][HDIM];
    __shared__ __align__(16) float h1E[WARPS_PER_CTA][HDIM];
    __shared__ __align__(16) float h1O[WARPS_PER_CTA][HDIM];
    __shared__ __align__(16) float h2E[WARPS_PER_CTA][HDIM];
    __shared__ __align__(16) float h2O[WARPS_PER_CTA][HDIM];
    __shared__ __align__(16) float xs[WARPS_PER_CTA][2][CHUNK * DIN];
    // Cross-layer weight matrices, ONE CTA-wide copy, [pair][lane]:
    // frees 64 registers per thread (slack) at the cost of LSU-pipe work.
    __shared__ __align__(16) ull wp1s[16][32];
    __shared__ __align__(16) ull wp2s[16][32];

    const int tid = threadIdx.x;
    const int w = tid >> 5;
    const int j = tid & 31;
    const int b = blockIdx.x * WARPS_PER_CTA + w;

    // zero h state
    h0E[w][j] = 0.0f; h0O[w][j] = 0.0f;
    h1E[w][j] = 0.0f; h1O[w][j] = 0.0f;
    h2E[w][j] = 0.0f; h2O[w][j] = 0.0f;

    // stage wp1/wp2 into shared (row jj of WihR layer l, pair p)
    for (int idx = tid; idx < 16 * 32; idx += WARPS_PER_CTA * 32) {
        int p = idx >> 5, jj = idx & 31;
        wp1s[p][jj] = reinterpret_cast<const ull*>(WihR + (0 * HDIM + jj) * HDIM)[p];
        wp2s[p][jj] = reinterpret_cast<const ull*>(WihR + (1 * HDIM + jj) * HDIM)[p];
    }
    __syncthreads();

    // ---- register weights: wx0 + three recurrent matrices (102 regs) ----
    ull wx0[3], wr0[16], wr1[16], wr2[16];
    {
        const ull* q = reinterpret_cast<const ull*>(Wih0 + j * DIN);
        wx0[0] = q[0]; wx0[1] = q[1]; wx0[2] = q[2];
    }
    {
        const ull* q0 = reinterpret_cast<const ull*>(Whh + (0 * HDIM + j) * HDIM);
        const ull* q1 = reinterpret_cast<const ull*>(Whh + (1 * HDIM + j) * HDIM);
        const ull* q2 = reinterpret_cast<const ull*>(Whh + (2 * HDIM + j) * HDIM);
#pragma unroll
        for (int k = 0; k < 16; k++) {
            wr0[k] = q0[k]; wr1[k] = q1[k]; wr2[k] = q2[k];
        }
    }
    const ull bp0 = pack2(bih[0 * HDIM + j] + bhh[0 * HDIM + j], 0.0f);
    const ull bp1 = pack2(bih[1 * HDIM + j] + bhh[1 * HDIM + j], 0.0f);
    const ull bp2 = pack2(bih[2 * HDIM + j] + bhh[2 * HDIM + j], 0.0f);

    const ull* wp1j = &wp1s[0][j];      // lane-strided base, stride 32 ull per pair
    const ull* wp2j = &wp2s[0][j];

    // ---- x staging: chunk 0 direct, chunk 1 prefetched into registers ----
    const float4* gx = reinterpret_cast<const float4*>(x + (size_t)b * (T_STEPS * DIN));
    float4* xs0 = reinterpret_cast<float4*>(&xs[w][0][0]);
    float4* xs1 = reinterpret_cast<float4*>(&xs[w][1][0]);

    xs0[j] = gx[j]; xs0[j + 32] = gx[j + 32]; xs0[j + 64] = gx[j + 64];
    CBAR();
    float4 pf0 = gx[96 + j], pf1 = gx[96 + j + 32], pf2 = gx[96 + j + 64];

    float h2last = 0.0f;

    // even timestep (pw=0, pr=1), store-ASAP; arrays alias-free
    auto iterE = [&](const float* xp) {
        float n0 = cell0(wx0, xp, wr0, &h0O[w][0], bp0);
        h0E[w][j] = n0;
        float n1 = cellS(wp1j, &h0O[w][0], wr1, &h1E[w][0], bp1);
        h1O[w][j] = n1;
        float n2 = cellS(wp2j, &h1E[w][0], wr2, &h2O[w][0], bp2);
        h2E[w][j] = n2;
    };
    // odd timestep (pw=1, pr=0)
    auto iterO = [&](const float* xp) {
        float n0 = cell0(wx0, xp, wr0, &h0E[w][0], bp0);
        h0O[w][j] = n0;
        float n1 = cellS(wp1j, &h0E[w][0], wr1, &h1O[w][0], bp1);
        h1E[w][j] = n1;
        float n2 = cellS(wp2j, &h1O[w][0], wr2, &h2E[w][0], bp2);
        h2O[w][j] = n2;
    };

    // ---- prologue peels ----
    {   // i = 0 (pw=0): only L0; h0[-1] = h0O = zeros
        float n0 = cell0(wx0, &xs[w][0][0 * DIN], wr0, &h0O[w][0], bp0);
        h0E[w][j] = n0;
    }
    {   // i = 1 (pw=1): L0 + L1; h1 prev = h1O = zeros
        float n0 = cell0(wx0, &xs[w][0][1 * DIN], wr0, &h0E[w][0], bp0);
        h0O[w][j] = n0;
        float n1 = cellS(wp1j, &h0E[w][0], wr1, &h1O[w][0], bp1);
        h1E[w][j] = n1;
    }

    // ---- chunk 0 (cold): i = 2 .. 63 ----
#pragma unroll 1
    for (int s = 2; s < CHUNK; s += 2) {
        iterE(&xs[w][0][s * DIN]);
        iterO(&xs[w][0][(s + 1) * DIN]);
    }

    // ---- main chunks 1 .. NCHUNK-1 (hot, unrolled x2) ----
#pragma unroll 1
    for (int c = 1; c < NCHUNK; c++) {
        {   // stage chunk c from prefetch regs, prefetch chunk c+1
            float4* dst = (c & 1) ? xs1 : xs0;
            dst[j] = pf0; dst[j + 32] = pf1; dst[j + 64] = pf2;
            CBAR();
            if (c < NCHUNK - 1) {
                pf0 = gx[(c + 1) * 96 + j];
                pf1 = gx[(c + 1) * 96 + j + 32];
                pf2 = gx[(c + 1) * 96 + j + 64];
            }
        }
        const float* xrow = (c & 1) ? &xs[w][1][0] : &xs[w][0][0];
#pragma unroll 2
        for (int s = 0; s < CHUNK; s += 2) {
            iterE(xrow + s * DIN);              // even global t
            iterO(xrow + (s + 1) * DIN);        // odd global t
        }
        CBAR();                                  // keep next chunk's staging stores below
    }

    // ---- epilogue peels ----
    {   // i = 2048 (pw=0, pr=1): L1(2047) + L2(2046)
        float n1 = cellS(wp1j, &h0O[w][0], wr1, &h1E[w][0], bp1);
        h1O[w][j] = n1;
        float n2 = cellS(wp2j, &h1E[w][0], wr2, &h2O[w][0], bp2);
        h2E[w][j] = n2;
    }
    {   // i = 2049 (pw=1, pr=0): L2(2047) -> final hidden state
        h2last = cellS(wp2j, &h1O[w][0], wr2, &h2E[w][0], bp2);
    }

    // ---- FC head: out[b,c] = sum_j h2last_j * fcw[c,j] + fcb[c] ----
    float s0v = h2last * fcw[0 * HDIM + j];
    float s1v = h2last * fcw[1 * HDIM + j];
    float s2v = h2last * fcw[2 * HDIM + j];
    float s3v = h2last * fcw[3 * HDIM + j];
    float s4v = h2last * fcw[4 * HDIM + j];
    float s5v = h2last * fcw[5 * HDIM + j];
#pragma unroll
    for (int off = 16; off; off >>= 1) {
        s0v += __shfl_xor_sync(0xffffffffu, s0v, off);
        s1v += __shfl_xor_sync(0xffffffffu, s1v, off);
        s2v += __shfl_xor_sync(0xffffffffu, s2v, off);
        s3v += __shfl_xor_sync(0xffffffffu, s3v, off);
        s4v += __shfl_xor_sync(0xffffffffu, s4v, off);
        s5v += __shfl_xor_sync(0xffffffffu, s5v, off);
    }
    float v = s0v;
    if (j == 1) v = s1v;
    if (j == 2) v = s2v;
    if (j == 3) v = s3v;
    if (j == 4) v = s4v;
    if (j == 5) v = s5v;
    if (j < 6) out[b * 6 + j] = v + fcb[j];
}

extern "C" void kernel_launch(void* const* d_in, const int* in_sizes, int n_in,
                              void* d_out, int out_size) {
    const float* x    = (const float*)d_in[0];
    const float* Wih0 = (const float*)d_in[1];
    const float* WihR = (const float*)d_in[2];
    const float* Whh  = (const float*)d_in[3];
    const float* bih  = (const float*)d_in[4];
    const float* bhh  = (const float*)d_in[5];
    const float* fcw  = (const float*)d_in[6];
    const float* fcb  = (const float*)d_in[7];

    const int B = in_sizes[0] / (T_STEPS * DIN);   // 512
    rnn3_fused_kernel<<<B / WARPS_PER_CTA, WARPS_PER_CTA * 32>>>(
        x, Wih0, WihR, Whh, bih, bhh, fcw, fcb, (float*)d_out);
}

// round 16
// speedup vs baseline: 1.3569x; 1.2606x over previous
#include <cuda_runtime.h>
#include <cstdint>
#include <cstddef>

typedef unsigned long long ull;

#define T_STEPS 2048
#define HDIM 32
#define DIN 6
#define WARPS_PER_CTA 4
#define CHUNK 64
#define NCHUNK (T_STEPS / CHUNK)

#define CBAR() asm volatile("" ::: "memory")

__device__ __forceinline__ ull fma2(ull a, ull b, ull c) {
    ull r;
    asm("fma.rn.f32x2 %0, %1, %2, %3;" : "=l"(r) : "l"(a), "l"(b), "l"(c));
    return r;
}
__device__ __forceinline__ ull add2(ull a, ull b) {
    ull r;
    asm("add.rn.f32x2 %0, %1, %2;" : "=l"(r) : "l"(a), "l"(b));
    return r;
}
__device__ __forceinline__ float hsum2(ull a) {
    float lo, hi;
    asm("mov.b64 {%0, %1}, %2;" : "=f"(lo), "=f"(hi) : "l"(a));
    return lo + hi;
}
__device__ __forceinline__ ull pack2(float lo, float hi) {
    ull r;
    asm("mov.b64 %0, {%1, %2};" : "=l"(r) : "f"(lo), "f"(hi));
    return r;
}
__device__ __forceinline__ float tanh_mufu(float x) {
    float r;
    asm("tanh.approx.f32 %0, %1;" : "=f"(r) : "f"(x));
    return r;
}

// RNN cell, both weight matrices in registers (layers 0-recur + 1)
__device__ __forceinline__ float cell(const ull (&wp)[16], const float* hin,
                                      const ull (&wr)[16], const float* hprev,
                                      ull biasp) {
    ull a0 = biasp, a1 = 0ull, a2 = 0ull, a3 = 0ull;
    const ulonglong2* hp = reinterpret_cast<const ulonglong2*>(hin);
    const ulonglong2* hr = reinterpret_cast<const ulonglong2*>(hprev);
#pragma unroll
    for (int p = 0; p < 8; p++) {
        ulonglong2 u = hp[p];           // LDS.128 broadcast
        a0 = fma2(u.x, wp[2 * p],     a0);
        a1 = fma2(u.y, wp[2 * p + 1], a1);
        ulonglong2 v = hr[p];
        a2 = fma2(v.x, wr[2 * p],     a2);
        a3 = fma2(v.y, wr[2 * p + 1], a3);
    }
    a0 = add2(add2(a0, a1), add2(a2, a3));
    return tanh_mufu(hsum2(a0));
}

// L2 cell: cross-layer matrix Wp2 from SHARED ([p][lane] ulonglong2, LDS.128,
// 4-phase conflict-free), recurrent Wr2 in registers. Frees 32 regs/thread.
__device__ __forceinline__ float cellS2(const ulonglong2* wps, const float* hin,
                                        const ull (&wr)[16], const float* hprev,
                                        ull biasp) {
    ull a0 = biasp, a1 = 0ull, a2 = 0ull, a3 = 0ull;
    const ulonglong2* hp = reinterpret_cast<const ulonglong2*>(hin);
    const ulonglong2* hr = reinterpret_cast<const ulonglong2*>(hprev);
#pragma unroll
    for (int p = 0; p < 8; p++) {
        ulonglong2 u = hp[p];
        ulonglong2 wv = wps[p * 32];    // LDS.128: (w[2p], w[2p+1]) for this lane
        a0 = fma2(u.x, wv.x, a0);
        a1 = fma2(u.y, wv.y, a1);
        ulonglong2 v = hr[p];
        a2 = fma2(v.x, wr[2 * p],     a2);
        a3 = fma2(v.y, wr[2 * p + 1], a3);
    }
    a0 = add2(add2(a0, a1), add2(a2, a3));
    return tanh_mufu(hsum2(a0));
}

// layer-0 cell: x-projection (D=6 -> 3 pairs) + recurrence, bias folded
__device__ __forceinline__ float cell0(const ull (&wx)[3], const float* xp,
                                       const ull (&wr)[16], const float* hprev,
                                       ull biasp) {
    const ull* xq = reinterpret_cast<const ull*>(xp);
    ull a0 = fma2(xq[0], wx[0], biasp);
    a0 = fma2(xq[1], wx[1], a0);
    a0 = fma2(xq[2], wx[2], a0);
    ull a1 = 0ull, a2 = 0ull;
    const ulonglong2* hr = reinterpret_cast<const ulonglong2*>(hprev);
#pragma unroll
    for (int p = 0; p < 8; p++) {
        ulonglong2 v = hr[p];
        a1 = fma2(v.x, wr[2 * p],     a1);
        a2 = fma2(v.y, wr[2 * p + 1], a2);
    }
    a0 = add2(a0, add2(a1, a2));
    return tanh_mufu(hsum2(a0));
}

__global__ void __launch_bounds__(WARPS_PER_CTA * 32, 1)
rnn3_fused_kernel(const float* __restrict__ x,
                  const float* __restrict__ Wih0,
                  const float* __restrict__ WihR,
                  const float* __restrict__ Whh,
                  const float* __restrict__ bih,
                  const float* __restrict__ bhh,
                  const float* __restrict__ fcw,
                  const float* __restrict__ fcb,
                  float* __restrict__ out) {
    __shared__ __align__(16) float hb[WARPS_PER_CTA][3][2][HDIM];       // [warp][layer][parity][h]
    __shared__ __align__(16) float xs[WARPS_PER_CTA][2][CHUNK * DIN];   // x staging, double buffered
    __shared__ __align__(16) ulonglong2 wp2s[8][32];                    // Wp2 (L2 cross), [pair2][lane]

    const int tid = threadIdx.x;
    const int w = tid >> 5;
    const int j = tid & 31;
    const int b = blockIdx.x * WARPS_PER_CTA + w;

    // zero h state (both parities)
    for (int q = tid; q < WARPS_PER_CTA * 3 * 2 * HDIM; q += WARPS_PER_CTA * 32)
        (&hb[0][0][0][0])[q] = 0.0f;

    // stage Wp2 (WihR layer 1) into shared: wp2s[p][jj] = (w_row_jj[2p], w_row_jj[2p+1])
    for (int idx = tid; idx < 8 * 32; idx += WARPS_PER_CTA * 32) {
        int p = idx >> 5, jj = idx & 31;
        const ull* q = reinterpret_cast<const ull*>(WihR + (1 * HDIM + jj) * HDIM);
        ulonglong2 v; v.x = q[2 * p]; v.y = q[2 * p + 1];
        wp2s[p][jj] = v;
    }
    __syncthreads();

    // ---- register weights: wx0 + wr0 + wp1 + wr1 + wr2 (134 regs; 32 freed) ----
    ull wx0[3], wr0[16], wp1[16], wr1[16], wr2[16];
    {
        const ull* q = reinterpret_cast<const ull*>(Wih0 + j * DIN);
        wx0[0] = q[0]; wx0[1] = q[1]; wx0[2] = q[2];
    }
    {
        const ull* q0 = reinterpret_cast<const ull*>(Whh  + (0 * HDIM + j) * HDIM);
        const ull* q1 = reinterpret_cast<const ull*>(Whh  + (1 * HDIM + j) * HDIM);
        const ull* q2 = reinterpret_cast<const ull*>(Whh  + (2 * HDIM + j) * HDIM);
        const ull* p1 = reinterpret_cast<const ull*>(WihR + (0 * HDIM + j) * HDIM);
#pragma unroll
        for (int k = 0; k < 16; k++) {
            wr0[k] = q0[k]; wr1[k] = q1[k]; wr2[k] = q2[k];
            wp1[k] = p1[k];
        }
    }
    const ull bp0 = pack2(bih[0 * HDIM + j] + bhh[0 * HDIM + j], 0.0f);
    const ull bp1 = pack2(bih[1 * HDIM + j] + bhh[1 * HDIM + j], 0.0f);
    const ull bp2 = pack2(bih[2 * HDIM + j] + bhh[2 * HDIM + j], 0.0f);

    const ulonglong2* wp2j = &wp2s[0][j];   // lane base, stride 32 per pair2

    float* h0 = &hb[w][0][0][0];
    float* h1 = &hb[w][1][0][0];
    float* h2 = &hb[w][2][0][0];

    // ---- x staging: chunk 0 direct, chunk 1 prefetched into registers ----
    const float4* gx = reinterpret_cast<const float4*>(x + (size_t)b * (T_STEPS * DIN));
    float4* xs0 = reinterpret_cast<float4*>(&xs[w][0][0]);
    float4* xs1 = reinterpret_cast<float4*>(&xs[w][1][0]);

    xs0[j] = gx[j]; xs0[j + 32] = gx[j + 32]; xs0[j + 64] = gx[j + 64];
    CBAR();
    float4 pf0 = gx[96 + j], pf1 = gx[96 + j + 32], pf2 = gx[96 + j + 64];

    float h2last = 0.0f;

    // one skewed iteration: L0 at t=i, L1 at t=i-1, L2 at t=i-2.
    // Stores at iteration end (cross-iter hoist stays alias-fenced -> no
    // register-greed spiral); intra-iteration interleave of the 3 cells is
    // legal AND now affordable with 32 freed registers.
    auto iter = [&](int pw, const float* xp) {
        const int pr = pw ^ 1;
        float n0 = cell0 (wx0,  xp,             wr0, h0 + pr * HDIM, bp0);
        float n1 = cell  (wp1,  h0 + pr * HDIM, wr1, h1 + pw * HDIM, bp1);
        float n2 = cellS2(wp2j, h1 + pw * HDIM, wr2, h2 + pr * HDIM, bp2);
        h0[pw * HDIM + j] = n0;
        h1[pr * HDIM + j] = n1;
        h2[pw * HDIM + j] = n2;
    };

    // ---- prologue peels ----
    {   // i = 0: only L0(0); h0[-1]=0 (parity 1 zeroed)
        float n0 = cell0(wx0, &xs[w][0][0 * DIN], wr0, h0 + HDIM, bp0);
        h0[j] = n0;
    }
    {   // i = 1: L0(1) + L1(0); h1[-1]=0 (parity 1 zeroed)
        float n0 = cell0(wx0, &xs[w][0][1 * DIN], wr0, h0, bp0);
        float n1 = cell (wp1, h0, wr1, h1 + HDIM, bp1);
        h0[HDIM + j] = n0;
        h1[j] = n1;
    }

    // ---- chunk 0 (cold): i = 2 .. 63 ----
#pragma unroll 1
    for (int s = 2; s < CHUNK; s += 2) {
        iter(0, &xs[w][0][s * DIN]);
        iter(1, &xs[w][0][(s + 1) * DIN]);
    }

    // ---- main chunks 1 .. NCHUNK-1 (hot, unrolled x4) ----
#pragma unroll 1
    for (int c = 1; c < NCHUNK; c++) {
        {   // stage chunk c from prefetch regs, prefetch chunk c+1
            float4* dst = (c & 1) ? xs1 : xs0;
            dst[j] = pf0; dst[j + 32] = pf1; dst[j + 64] = pf2;
            CBAR();
            if (c < NCHUNK - 1) {
                pf0 = gx[(c + 1) * 96 + j];
                pf1 = gx[(c + 1) * 96 + j + 32];
                pf2 = gx[(c + 1) * 96 + j + 64];
            }
        }
        const float* xrow = (c & 1) ? &xs[w][1][0] : &xs[w][0][0];
#pragma unroll 4
        for (int s = 0; s < CHUNK; s += 2) {
            iter(0, xrow + s * DIN);            // even global t
            iter(1, xrow + (s + 1) * DIN);      // odd global t
        }
        CBAR();                                  // keep next chunk's staging stores below
    }

    // ---- epilogue peels ----
    {   // i = 2048 (pw=0, pr=1): L1(2047) + L2(2046)
        float n1 = cell  (wp1,  h0 + HDIM, wr1, h1,        bp1);
        float n2 = cellS2(wp2j, h1,        wr2, h2 + HDIM, bp2);
        h1[HDIM + j] = n1;
        h2[j] = n2;
    }
    {   // i = 2049 (pw=1, pr=0): L2(2047) -> final hidden state, keep in register
        h2last = cellS2(wp2j, h1 + HDIM, wr2, h2, bp2);
    }

    // ---- FC head: out[b,c] = sum_j h2last_j * fcw[c,j] + fcb[c] ----
    float s0v = h2last * fcw[0 * HDIM + j];
    float s1v = h2last * fcw[1 * HDIM + j];
    float s2v = h2last * fcw[2 * HDIM + j];
    float s3v = h2last * fcw[3 * HDIM + j];
    float s4v = h2last * fcw[4 * HDIM + j];
    float s5v = h2last * fcw[5 * HDIM + j];
#pragma unroll
    for (int off = 16; off; off >>= 1) {
        s0v += __shfl_xor_sync(0xffffffffu, s0v, off);
        s1v += __shfl_xor_sync(0xffffffffu, s1v, off);
        s2v += __shfl_xor_sync(0xffffffffu, s2v, off);
        s3v += __shfl_xor_sync(0xffffffffu, s3v, off);
        s4v += __shfl_xor_sync(0xffffffffu, s4v, off);
        s5v += __shfl_xor_sync(0xffffffffu, s5v, off);
    }
    float v = s0v;
    if (j == 1) v = s1v;
    if (j == 2) v = s2v;
    if (j == 3) v = s3v;
    if (j == 4) v = s4v;
    if (j == 5) v = s5v;
    if (j < 6) out[b * 6 + j] = v + fcb[j];
}

extern "C" void kernel_launch(void* const* d_in, const int* in_sizes, int n_in,
                              void* d_out, int out_size) {
    const float* x    = (const float*)d_in[0];
    const float* Wih0 = (const float*)d_in[1];
    const float* WihR = (const float*)d_in[2];
    const float* Whh  = (const float*)d_in[3];
    const float* bih  = (const float*)d_in[4];
    const float* bhh  = (const float*)d_in[5];
    const float* fcw  = (const float*)d_in[6];
    const float* fcb  = (const float*)d_in[7];

    const int B = in_sizes[0] / (T_STEPS * DIN);   // 512
    rnn3_fused_kernel<<<B / WARPS_PER_CTA, WARPS_PER_CTA * 32>>>(
        x, Wih0, WihR, Whh, bih, bhh, fcw, fcb, (float*)d_out);
}